// round 4
// baseline (speedup 1.0000x reference)
#include <cuda_runtime.h>
#include <math.h>

#define EE 25440
#define NN 160

// ---------------- device scratch (static, no runtime alloc) ----------------
__device__ float g_x_ii[NN * 1568];
__device__ float g_x_ij[(size_t)EE * 1568];
__device__ float g_h_ii_c[NN * 128], g_h_ii_b[NN * 128];
__device__ float g_h_ij_c[EE * 128], g_h_ij_b[EE * 128];
__device__ float g_w_ii[NN * 1792];
__device__ float g_w_ij[(size_t)EE * 1792];
__device__ float g_b_ii[NN * 14], g_b_ij[EE * 14];
__device__ float g_raw_ii[NN * 196];
__device__ float g_raw_ij[EE * 196];
__device__ float g_w3j[1225];

// ---------------- constant tables ----------------
// feature irreps: l = {0,1,1,2,2,3,3,4,4}
__constant__ int c_XO[10] = {0, 32, 128, 224, 384, 544, 768, 992, 1280, 1568};
__constant__ int c_FO[9]  = {0, 64, 256, 448, 768, 1088, 1536, 1984, 2560};
__constant__ int c_D[9]   = {1, 3, 3, 5, 5, 7, 7, 9, 9};
__constant__ int c_MUL[3] = {3, 2, 1};   // out irrep multiplicities (index = l)
// o3 task table: 8*d tasks per segment, cumulative
__constant__ int c_TB[10] = {0, 8, 32, 56, 96, 136, 192, 248, 320, 392};

// 19 expansion paths, in reference INSTR order
__constant__ int P_I[19]  = {0,0,0,1,1,1,1,2,2,3,3,4,4,4,4,5,5,6,8};
__constant__ int P_J[19]  = {0,1,2,0,1,1,2,1,2,1,2,0,1,2,2,1,2,2,2};
__constant__ int P_K[19]  = {0,1,2,1,0,2,1,1,2,2,1,2,1,0,2,2,1,2,2};
__constant__ int P_WI[19] = {0,288,416,448,640,832,896,960,1088,1120,1184,1248,1344,1472,1568,1600,1664,1728,1760};
__constant__ int P_RO[19] = {0,9,13,14,32,50,56,62,74,77,87,97,112,132,147,152,166,180,187};
__constant__ int P_BO[19] = {0,9,13,-1,-1,-1,-1,-1,-1,-1,-1,-1,-1,-1,-1,-1,-1,-1,-1};
// wigner tensor (lj,lk,li), sizes (2lj+1)(2lk+1)(2li+1), flat offsets into g_w3j
__constant__ int K_OFF[19]= {0,1,10,35,44,53,98,143,170,245,320,395,420,465,490,615,720,825,1000};
__constant__ int K_L3[19] = {0,0,0,1,1,1,1,1,1,2,2,2,2,2,2,3,3,3,4};  // li per path
__constant__ int W_L1[19] = {0,1,2,0,1,1,2,1,2,1,2,0,1,2,2,1,2,2,2};  // lj per path
__constant__ int W_L2[19] = {0,1,2,1,0,2,1,1,2,2,1,2,1,0,2,2,1,2,2};  // lk per path

// ---------------- Wigner 3j on device (fp64, exact port of reference) -----
struct cplx { double re, im; };

__device__ __forceinline__ double dfac(int n) {
    double r = 1.0;
    for (int i = 2; i <= n; i++) r *= (double)i;
    return r;
}

__device__ double su2_cg(int j1, int m1, int j2, int m2, int j3, int m3) {
    int vmin = max(max(j2 - j1 + m3, m1 - j1), 0);
    int vmax = min(min(j2 + j3 + m1, j3 - j1 + j2), j3 + m3);
    if (vmax < vmin) return 0.0;
    double c = sqrt((2.0 * j3 + 1.0) * dfac(j3 + j1 - j2) * dfac(j3 - j1 + j2) * dfac(j1 + j2 - j3)
                    * dfac(j3 + m3) * dfac(j3 - m3)
                    / (dfac(j1 + j2 + j3 + 1) * dfac(j1 - m1) * dfac(j1 + m1)
                       * dfac(j2 - m2) * dfac(j2 + m2)));
    double s = 0.0;
    for (int v = vmin; v <= vmax; v++) {
        double t = dfac(j2 + j3 + m1 - v) * dfac(j1 - m1 + v)
                   / (dfac(v) * dfac(j3 - j1 + j2 - v) * dfac(j3 + m3 - v) * dfac(v + j1 - j2 - m3));
        s += (((v + j2 + m2) & 1) ? -t : t);
    }
    return c * s;
}

// q(l)[row][col] including the (-i)^l factor
__device__ cplx q_entry(int l, int row, int col) {
    int m = row - l;
    const double r2 = 0.70710678118654752440;
    double re = 0.0, im = 0.0;
    if (m < 0) {
        if (col == l - m) re = r2;
        else if (col == l + m) im = -r2;
    } else if (m == 0) {
        if (col == l) re = 1.0;
    } else {
        double sg = (m & 1) ? -1.0 : 1.0;
        if (col == l + m) re = sg * r2;
        else if (col == l - m) im = sg * r2;
    }
    double a = re, b = im;
    switch (l & 3) {              // multiply by (-i)^l
        case 0: break;
        case 1: { double t = a; a = b;  b = -t; } break;
        case 2: a = -a; b = -b; break;
        case 3: { double t = a; a = -b; b = t; } break;
    }
    cplx q; q.re = a; q.im = b; return q;
}

__global__ void k_wigner() {
    int p = blockIdx.x;
    int l1 = W_L1[p], l2 = W_L2[p], l3 = K_L3[p];
    int d1 = 2 * l1 + 1, d2 = 2 * l2 + 1, d3 = 2 * l3 + 1;
    int nout = d1 * d2 * d3;
    double inv = 1.0 / sqrt(2.0 * l3 + 1.0);
    for (int o = threadIdx.x; o < nout; o += blockDim.x) {
        int j = o / (d2 * d3);
        int rem = o % (d2 * d3);
        int lc = rem / d3;
        int m = rem % d3;
        // q(l)[row][col] is nonzero only for row in {col, 2l-col}
        int ic[2] = { j, d1 - 1 - j };
        int kc[2] = { lc, d2 - 1 - lc };
        int ni = (ic[1] == ic[0]) ? 1 : 2;
        int nk = (kc[1] == kc[0]) ? 1 : 2;
        double acc = 0.0;
        for (int ii = 0; ii < ni; ii++)
            for (int kk = 0; kk < nk; kk++) {
                int i = ic[ii], k = kc[kk];
                int n = i + k - l1 - l2 + l3;     // m3 = m1 + m2
                if (n < 0 || n >= d3) continue;
                double cg = su2_cg(l1, i - l1, l2, k - l2, l3, i - l1 + k - l2);
                if (cg == 0.0) continue;
                cplx q1 = q_entry(l1, i, j);
                cplx q2 = q_entry(l2, k, lc);
                cplx q3 = q_entry(l3, n, m);
                q3.im = -q3.im;                   // conj
                double re12 = q1.re * q2.re - q1.im * q2.im;
                double im12 = q1.re * q2.im + q1.im * q2.re;
                double re = re12 * q3.re - im12 * q3.im;
                acc += re * cg;
            }
        g_w3j[K_OFF[p] + o] = (float)(acc * inv);
    }
}

// ---------------- o3 linear: x = blockdiag(W) @ f * (1/8) ------------------
// W (73.7 KB) + one feature row (12.5 KB) live in dynamic smem; persistent
// blocks loop over rows. Lane task = (segment s, o-quad q, m); per u:
// 1 broadcast LDS (f) + 1 conflict-free LDS.128 (W) + 4 FFMA.
__global__ __launch_bounds__(256) void k_o3(const float* __restrict__ f,
                                            const float* __restrict__ W,
                                            int which, int nrows) {
    extern __shared__ float sh[];
    float* Wsh = sh;            // 18432 floats
    float* fsh = sh + 18432;    // 3136 floats
    for (int t = threadIdx.x; t < 4608; t += 256)
        ((float4*)Wsh)[t] = ((const float4*)W)[t];
    float* xbase = which ? g_x_ij : g_x_ii;
    for (int b = blockIdx.x; b < nrows; b += gridDim.x) {
        __syncthreads();
        const float4* fr = (const float4*)(f + (size_t)b * 3136);
        for (int t = threadIdx.x; t < 784; t += 256) ((float4*)fsh)[t] = fr[t];
        __syncthreads();
        float* xo = xbase + (size_t)b * 1568;
        for (int t = threadIdx.x; t < 392; t += 256) {
            int s = 0;
            while (s < 8 && t >= c_TB[s + 1]) s++;
            int loc = t - c_TB[s];
            int q = loc & 7;       // o-quad
            int m = loc >> 3;
            int d = c_D[s];
            const float4* w4 = (const float4*)(Wsh + s * 2048) + q;
            const float* fp = fsh + c_FO[s] + m;
            float4 acc = make_float4(0.f, 0.f, 0.f, 0.f);
            #pragma unroll 4
            for (int u = 0; u < 64; u++) {
                float fv = fp[u * d];
                float4 w = w4[u * 8];
                acc.x += fv * w.x; acc.y += fv * w.y;
                acc.z += fv * w.z; acc.w += fv * w.w;
            }
            int o0 = q * 4;
            float* xp = xo + c_XO[s] + m;
            xp[(o0 + 0) * d] = acc.x * 0.125f;
            xp[(o0 + 1) * d] = acc.y * 0.125f;
            xp[(o0 + 2) * d] = acc.z * 0.125f;
            xp[(o0 + 3) * d] = acc.w * 0.125f;
        }
    }
}

// ---------------- MLP hidden layers ----------------------------------------
__device__ __forceinline__ float silu(float v) { return v / (1.f + expf(-v)); }

__global__ __launch_bounds__(256) void k_mlp_ii(const float* __restrict__ embed,
        const float* __restrict__ w1c, const float* __restrict__ b1c,
        const float* __restrict__ w1b, const float* __restrict__ b1b) {
    __shared__ float esh[128];
    int b = blockIdx.x;
    if (threadIdx.x < 128) esh[threadIdx.x] = embed[b * 128 + threadIdx.x];
    __syncthreads();
    int c = threadIdx.x & 127, sel = threadIdx.x >> 7;
    const float* Wm = sel ? w1b : w1c;
    float acc = (sel ? b1b : b1c)[c];
    for (int k = 0; k < 128; k++) acc += esh[k] * Wm[k * 128 + c];
    float* out = sel ? g_h_ii_b : g_h_ii_c;
    out[b * 128 + c] = silu(acc);
}

__global__ __launch_bounds__(256) void k_mlp_ij(const float* __restrict__ embed,
        const float* __restrict__ w1c, const float* __restrict__ b1c,
        const float* __restrict__ w1b, const float* __restrict__ b1b) {
    __shared__ float Psh[32][256];
    int e0 = blockIdx.x * 32;
    for (int idx = threadIdx.x; idx < 32 * 256; idx += 256) {
        int e = idx >> 8, k = idx & 255;
        int ge = e0 + e;
        int s = ge / 159, rm = ge - s * 159;
        int dn = rm + (rm >= s);
        Psh[e][k] = (k < 128) ? embed[s * 128 + k] : embed[dn * 128 + (k - 128)];
    }
    __syncthreads();
    int c = threadIdx.x & 127, sel = threadIdx.x >> 7;
    const float* Wm = sel ? w1b : w1c;
    float bv = (sel ? b1b : b1c)[c];
    float acc[32];
    #pragma unroll
    for (int e = 0; e < 32; e++) acc[e] = bv;
    for (int k = 0; k < 256; k += 4) {
        float w0 = Wm[k * 128 + c];
        float w1 = Wm[(k + 1) * 128 + c];
        float w2 = Wm[(k + 2) * 128 + c];
        float w3 = Wm[(k + 3) * 128 + c];
        #pragma unroll
        for (int e = 0; e < 32; e++) {
            float4 p = *(const float4*)&Psh[e][k];
            acc[e] += p.x * w0 + p.y * w1 + p.z * w2 + p.w * w3;
        }
    }
    float* out = sel ? g_h_ij_b : g_h_ij_c;
    for (int e = 0; e < 32; e++)
        out[(size_t)(e0 + e) * 128 + c] = silu(acc[e]);
}

// ---------------- second MLP layer: weights = H @ W2 + b2 ------------------
__global__ __launch_bounds__(256) void k_w2(const float* __restrict__ W2,
                                            const float* __restrict__ b2,
                                            int nrows, int which) {
    const float* H = which ? g_h_ij_c : g_h_ii_c;
    float* out = which ? g_w_ij : g_w_ii;
    __shared__ float Hsh[64][128];
    int r0 = blockIdx.x * 64, c0 = blockIdx.y * 64;
    for (int idx = threadIdx.x; idx < 64 * 128; idx += 256) {
        int r = idx >> 7, k = idx & 127;
        int gr = r0 + r;
        Hsh[r][k] = (gr < nrows) ? H[(size_t)gr * 128 + k] : 0.f;
    }
    __syncthreads();
    int c = c0 + (threadIdx.x & 63);
    int eg = threadIdx.x >> 6;
    float bv = b2[c];
    float acc[16];
    #pragma unroll
    for (int i = 0; i < 16; i++) acc[i] = bv;
    for (int k = 0; k < 128; k += 4) {
        float w0 = W2[(size_t)k * 1792 + c];
        float w1 = W2[(size_t)(k + 1) * 1792 + c];
        float w2 = W2[(size_t)(k + 2) * 1792 + c];
        float w3 = W2[(size_t)(k + 3) * 1792 + c];
        #pragma unroll
        for (int i = 0; i < 16; i++) {
            float4 h = *(const float4*)&Hsh[eg * 16 + i][k];
            acc[i] += h.x * w0 + h.y * w1 + h.z * w2 + h.w * w3;
        }
    }
    for (int i = 0; i < 16; i++) {
        int gr = r0 + eg * 16 + i;
        if (gr < nrows) out[(size_t)gr * 1792 + c] = acc[i];
    }
}

// biases = Hb @ Wb2 + bb2   (tiny: 14 cols)
__global__ void k_wb(const float* __restrict__ Wb, const float* __restrict__ bb,
                     int nrows, int which) {
    const float* H = which ? g_h_ij_b : g_h_ii_b;
    float* out = which ? g_b_ij : g_b_ii;
    int g = blockIdx.x * 256 + threadIdx.x;
    if (g >= nrows * 14) return;
    int r = g / 14, c = g - r * 14;
    float acc = bb[c];
    const float* h = H + (size_t)r * 128;
    for (int k = 0; k < 128; k++) acc += h[k] * Wb[k * 14 + c];
    out[g] = acc;
}

// ---------------- expansion (stage A: 32-dots; stage B: wigner contraction)
__global__ __launch_bounds__(256) void k_exp(int which) {
    __shared__ float wsh[1792];
    __shared__ float xsh[1568];
    __shared__ float w3sh[1225];
    __shared__ float rsh[196];
    __shared__ float bsh[14];
    int b = blockIdx.x;
    int tid = threadIdx.x;
    const float4* wr = (const float4*)((which ? g_w_ij : g_w_ii) + (size_t)b * 1792);
    const float4* xr = (const float4*)((which ? g_x_ij : g_x_ii) + (size_t)b * 1568);
    const float* br = (which ? g_b_ij : g_b_ii) + (size_t)b * 14;
    for (int t = tid; t < 448; t += 256) ((float4*)wsh)[t] = wr[t];
    for (int t = tid; t < 392; t += 256) ((float4*)xsh)[t] = xr[t];
    for (int t = tid; t < 1225; t += 256) w3sh[t] = g_w3j[t];
    if (tid < 14) bsh[tid] = br[tid];
    __syncthreads();

    // stage A: 196 r-slots, each a 32-element dot
    for (int rr = tid; rr < 196; rr += 256) {
        int p = 18;
        while (rr < P_RO[p]) p--;
        int loc = rr - P_RO[p];
        int li = K_L3[p];
        int d = 2 * li + 1;
        int uv = loc / d, kk = loc - uv * d;
        int muv = c_MUL[P_J[p]] * c_MUL[P_K[p]];
        const float* wp = wsh + P_WI[p] + uv;
        const float* xp = xsh + c_XO[P_I[p]] + kk;
        float acc = 0.f;
        #pragma unroll 8
        for (int w = 0; w < 32; w++) acc += wp[w * muv] * xp[w * d];
        if (li == 0) acc += bsh[P_BO[p] + uv];
        rsh[rr] = acc * 0.03125f;                  // fold 1/mi
    }
    __syncthreads();

    // stage B: 196 outputs
    float* raw = (which ? g_raw_ij : g_raw_ii) + (size_t)b * 196;
    for (int o = tid; o < 196; o += 256) {
        int row = o / 14, col = o - row * 14;
        int j, u, a;
        if (row < 3)      { j = 0; u = row; a = 0; }
        else if (row < 9) { j = 1; u = (row - 3) / 3; a = (row - 3) % 3; }
        else              { j = 2; u = 0; a = row - 9; }
        int k2, v, b2;
        if (col < 3)      { k2 = 0; v = col; b2 = 0; }
        else if (col < 9) { k2 = 1; v = (col - 3) / 3; b2 = (col - 3) % 3; }
        else              { k2 = 2; v = 0; b2 = col - 9; }
        float acc = 0.f;
        for (int p = 0; p < 19; p++) {
            if (P_J[p] != j || P_K[p] != k2) continue;
            int d = 2 * K_L3[p] + 1;
            int dk = 2 * k2 + 1;
            const float* w3 = w3sh + K_OFF[p] + (a * dk + b2) * d;
            const float* rp = rsh + P_RO[p] + (u * c_MUL[k2] + v) * d;
            for (int kk = 0; kk < d; kk++) acc += w3[kk] * rp[kk];
        }
        raw[o] = acc;
    }
}

// ---------------- symmetrize + write output --------------------------------
__global__ void k_sym(float* __restrict__ out) {
    int g = blockIdx.x * 256 + threadIdx.x;
    const int DIAG = NN * 196;
    const int TOT = DIAG + EE * 196;
    if (g >= TOT) return;
    if (g < DIAG) {
        int b = g / 196, o = g - b * 196;
        int r = o / 14, c = o - r * 14;
        out[g] = 0.5f * (g_raw_ii[b * 196 + o] + g_raw_ii[b * 196 + c * 14 + r]);
    } else {
        int gg = g - DIAG;
        int e = gg / 196, o = gg - e * 196;
        int r = o / 14, c = o - r * 14;
        int s = e / 159, rm = e - s * 159;
        int d = rm + (rm >= s);
        int rev = d * 159 + (s < d ? s : s - 1);   // reverse-edge index
        out[g] = 0.5f * (g_raw_ij[(size_t)e * 196 + o] + g_raw_ij[(size_t)rev * 196 + c * 14 + r]);
    }
}

// ---------------- launch ----------------------------------------------------
extern "C" void kernel_launch(void* const* d_in, const int* in_sizes, int n_in,
                              void* d_out, int out_size) {
    const float* fii      = (const float*)d_in[0];
    const float* fij      = (const float*)d_in[1];
    const float* embed    = (const float*)d_in[2];
    // d_in[3] = edge_index_full (unused: full-graph structure is closed-form)
    const float* wii      = (const float*)d_in[4];
    const float* wij      = (const float*)d_in[5];
    const float* ii_fc_w1 = (const float*)d_in[6];
    const float* ii_fc_b1 = (const float*)d_in[7];
    const float* ii_fc_w2 = (const float*)d_in[8];
    const float* ii_fc_b2 = (const float*)d_in[9];
    const float* ii_fb_w1 = (const float*)d_in[10];
    const float* ii_fb_b1 = (const float*)d_in[11];
    const float* ii_fb_w2 = (const float*)d_in[12];
    const float* ii_fb_b2 = (const float*)d_in[13];
    const float* ij_fc_w1 = (const float*)d_in[14];
    const float* ij_fc_b1 = (const float*)d_in[15];
    const float* ij_fc_w2 = (const float*)d_in[16];
    const float* ij_fc_b2 = (const float*)d_in[17];
    const float* ij_fb_w1 = (const float*)d_in[18];
    const float* ij_fb_b1 = (const float*)d_in[19];
    const float* ij_fb_w2 = (const float*)d_in[20];
    const float* ij_fb_b2 = (const float*)d_in[21];
    float* out = (float*)d_out;

    const int O3_SMEM = (18432 + 3136) * 4;   // 86272 B dynamic smem
    static int smem_set = 0;
    if (!smem_set) {
        cudaFuncSetAttribute(k_o3, cudaFuncAttributeMaxDynamicSharedMemorySize, O3_SMEM);
        smem_set = 1;
    }

    k_wigner<<<19, 64>>>();
    k_o3<<<NN, 256, O3_SMEM>>>(fii, wii, 0, NN);
    k_o3<<<296, 256, O3_SMEM>>>(fij, wij, 1, EE);
    k_mlp_ii<<<NN, 256>>>(embed, ii_fc_w1, ii_fc_b1, ii_fb_w1, ii_fb_b1);
    k_mlp_ij<<<EE / 32, 256>>>(embed, ij_fc_w1, ij_fc_b1, ij_fb_w1, ij_fb_b1);
    dim3 gii((NN + 63) / 64, 28), gij((EE + 63) / 64, 28);
    k_w2<<<gii, 256>>>(ii_fc_w2, ii_fc_b2, NN, 0);
    k_w2<<<gij, 256>>>(ij_fc_w2, ij_fc_b2, EE, 1);
    k_wb<<<(NN * 14 + 255) / 256, 256>>>(ii_fb_w2, ii_fb_b2, NN, 0);
    k_wb<<<(EE * 14 + 255) / 256, 256>>>(ij_fb_w2, ij_fb_b2, EE, 1);
    k_exp<<<NN, 256>>>(0);
    k_exp<<<EE, 256>>>(1);
    k_sym<<<((NN + EE) * 196 + 255) / 256, 256>>>(out);
}